// round 1
// baseline (speedup 1.0000x reference)
#include <cuda_runtime.h>
#include <math.h>

// Problem constants: x [B=16, nH=16, hd=64, H=64, W=64] fp32
#define N_ROWS 16384      // B*nH*hd
#define HW     4096       // H*W
#define HW4    1024       // HW / 4
#define HD     64
#define LSEQ   16         // nH = attention sequence length
#define BN     4          // bottleneck
#define NHEADS 2
#define DH     2

__device__ float g_pooled[N_ROWS];
__device__ float g_delta[N_ROWS];

// ---------------------------------------------------------------------------
// Kernel 1: mean over H*W for each (b, nH, hd) row. One block per row.
// ---------------------------------------------------------------------------
__global__ void pool_kernel(const float4* __restrict__ x)
{
    const int row = blockIdx.x;
    const float4* p = x + (size_t)row * HW4;

    float s = 0.0f;
    #pragma unroll
    for (int k = threadIdx.x; k < HW4; k += 128) {
        float4 v = p[k];
        s += (v.x + v.y) + (v.z + v.w);
    }
    // warp reduce
    #pragma unroll
    for (int off = 16; off > 0; off >>= 1)
        s += __shfl_down_sync(0xffffffffu, s, off);

    __shared__ float ws[4];
    if ((threadIdx.x & 31) == 0) ws[threadIdx.x >> 5] = s;
    __syncthreads();
    if (threadIdx.x == 0)
        g_pooled[row] = (ws[0] + ws[1] + ws[2] + ws[3]) * (1.0f / (float)HW);
}

// ---------------------------------------------------------------------------
// Kernel 2: compress -> MHA(L=16, E=4, h=2) -> out_proj -> expand -> LN,
// producing delta[16384]. One block, 256 threads; thread t = (b, l).
// ---------------------------------------------------------------------------
__global__ void tiny_attn_kernel(
    const float* __restrict__ cw,  const float* __restrict__ cb,
    const float* __restrict__ ipw, const float* __restrict__ ipb,
    const float* __restrict__ opw, const float* __restrict__ opb,
    const float* __restrict__ ew,  const float* __restrict__ eb,
    const float* __restrict__ lnw, const float* __restrict__ lnb,
    const float* __restrict__ gate)
{
    __shared__ float s_cw[BN * HD];      // compress_w [4,64]
    __shared__ float s_cb[BN];
    __shared__ float s_ipw[3 * BN * BN]; // in_proj_w [12,4]
    __shared__ float s_ipb[3 * BN];
    __shared__ float s_opw[BN * BN];     // out_proj_w [4,4]
    __shared__ float s_opb[BN];
    __shared__ float s_ew[HD * BN];      // expand_w [64,4]
    __shared__ float s_eb[HD];
    __shared__ float s_lnw[HD];
    __shared__ float s_lnb[HD];
    __shared__ float s_gate;
    __shared__ float s_k[256][BN];
    __shared__ float s_v[256][BN];

    const int t = threadIdx.x;           // 0..255
    // cooperative weight loads
    s_cw[t] = cw[t];
    s_ew[t] = ew[t];
    if (t < BN)        s_cb[t]  = cb[t];
    if (t < 3*BN*BN)   s_ipw[t] = ipw[t];
    if (t < 3*BN)      s_ipb[t] = ipb[t];
    if (t < BN*BN)     s_opw[t] = opw[t];
    if (t >= 64 && t < 64 + BN) s_opb[t - 64] = opb[t - 64];
    if (t < HD)  s_eb[t]  = eb[t];
    if (t >= 64 && t < 128) s_lnw[t - 64] = lnw[t - 64];
    if (t >= 128 && t < 192) s_lnb[t - 128] = lnb[t - 128];
    if (t == 255) s_gate = gate[0];
    __syncthreads();

    const int b = t >> 4;
    const float* prow = g_pooled + t * HD;

    // ---- compress: xc[4] = pooled_row @ compress_w.T + cb ----
    float xc0 = s_cb[0], xc1 = s_cb[1], xc2 = s_cb[2], xc3 = s_cb[3];
    #pragma unroll
    for (int i = 0; i < HD; i++) {
        float p = prow[i];
        xc0 += p * s_cw[i];
        xc1 += p * s_cw[HD + i];
        xc2 += p * s_cw[2*HD + i];
        xc3 += p * s_cw[3*HD + i];
    }
    float xc[BN] = {xc0, xc1, xc2, xc3};

    // ---- qkv = xc @ in_proj_w.T + in_proj_b ----
    float qkv[12];
    #pragma unroll
    for (int r = 0; r < 12; r++) {
        float a = s_ipb[r];
        #pragma unroll
        for (int c = 0; c < BN; c++) a += s_ipw[r * BN + c] * xc[c];
        qkv[r] = a;
    }
    #pragma unroll
    for (int c = 0; c < BN; c++) {
        s_k[t][c] = qkv[4 + c];
        s_v[t][c] = qkv[8 + c];
    }
    __syncthreads();

    // ---- attention per head (h=2, dh=2, keys = 16 tokens of same batch) ----
    const float scale = 0.7071067811865475f;  // 1/sqrt(dh=2)
    float o[BN];
    #pragma unroll
    for (int h = 0; h < NHEADS; h++) {
        const float q0 = qkv[2*h], q1 = qkv[2*h + 1];
        float sc[LSEQ];
        float mx = -1e30f;
        #pragma unroll
        for (int j = 0; j < LSEQ; j++) {
            int kt = (b << 4) + j;
            float s = (q0 * s_k[kt][2*h] + q1 * s_k[kt][2*h + 1]) * scale;
            sc[j] = s;
            mx = fmaxf(mx, s);
        }
        float den = 0.0f, o0 = 0.0f, o1 = 0.0f;
        #pragma unroll
        for (int j = 0; j < LSEQ; j++) {
            int kt = (b << 4) + j;
            float e = __expf(sc[j] - mx);
            den += e;
            o0 += e * s_v[kt][2*h];
            o1 += e * s_v[kt][2*h + 1];
        }
        float inv = 1.0f / den;
        o[2*h]     = o0 * inv;
        o[2*h + 1] = o1 * inv;
    }

    // ---- out_proj ----
    float xa[BN];
    #pragma unroll
    for (int e = 0; e < BN; e++) {
        float a = s_opb[e];
        #pragma unroll
        for (int f = 0; f < BN; f++) a += s_opw[e * BN + f] * o[f];
        xa[e] = a;
    }

    // ---- expand + residual + layernorm -> delta ----
    float y[HD];
    float mu = 0.0f;
    const float gv = s_gate;
    #pragma unroll
    for (int i = 0; i < HD; i++) {
        float ex = s_eb[i];
        #pragma unroll
        for (int f = 0; f < BN; f++) ex += s_ew[i * BN + f] * xa[f];
        float yv = prow[i] + gv * ex;
        y[i] = yv;
        mu += yv;
    }
    mu *= (1.0f / (float)HD);
    float var = 0.0f;
    #pragma unroll
    for (int i = 0; i < HD; i++) {
        float d = y[i] - mu;
        var += d * d;
    }
    var *= (1.0f / (float)HD);
    float inv = rsqrtf(var + 1e-5f);
    #pragma unroll
    for (int i = 0; i < HD; i++) {
        float outv = (y[i] - mu) * inv * s_lnw[i] + s_lnb[i];
        g_delta[t * HD + i] = outv - prow[i];
    }
}

// ---------------------------------------------------------------------------
// Kernel 3: out = x + delta[row], row = linear/4096. float4 streaming.
// ---------------------------------------------------------------------------
__global__ void add_kernel(const float4* __restrict__ x, float4* __restrict__ out,
                           int total4)
{
    int idx = blockIdx.x * blockDim.x + threadIdx.x;
    const int stride = gridDim.x * blockDim.x;
    for (; idx < total4; idx += stride) {
        float d = __ldg(g_delta + (idx >> 10));
        float4 v = x[idx];
        v.x += d; v.y += d; v.z += d; v.w += d;
        out[idx] = v;
    }
}

// ---------------------------------------------------------------------------
extern "C" void kernel_launch(void* const* d_in, const int* in_sizes, int n_in,
                              void* d_out, int out_size)
{
    const float* x   = (const float*)d_in[0];
    const float* cw  = (const float*)d_in[1];
    const float* cb  = (const float*)d_in[2];
    const float* ipw = (const float*)d_in[3];
    const float* ipb = (const float*)d_in[4];
    const float* opw = (const float*)d_in[5];
    const float* opb = (const float*)d_in[6];
    const float* ew  = (const float*)d_in[7];
    const float* eb  = (const float*)d_in[8];
    const float* lnw = (const float*)d_in[9];
    const float* lnb = (const float*)d_in[10];
    const float* gate= (const float*)d_in[11];
    float* out = (float*)d_out;

    pool_kernel<<<N_ROWS, 128>>>((const float4*)x);
    tiny_attn_kernel<<<1, 256>>>(cw, cb, ipw, ipb, opw, opb, ew, eb, lnw, lnb, gate);

    const int total4 = (N_ROWS * HW) / 4;  // 16,777,216
    add_kernel<<<8192, 256>>>((const float4*)x, (float4*)out, total4);
}

// round 2
// speedup vs baseline: 1.0229x; 1.0229x over previous
#include <cuda_runtime.h>
#include <math.h>

// Problem constants: x [B=16, nH=16, hd=64, H=64, W=64] fp32
#define N_ROWS 16384      // B*nH*hd
#define HW     4096       // H*W
#define HW4    1024       // HW / 4
#define HD     64
#define LSEQ   16         // nH = attention sequence length
#define BN     4          // bottleneck
#define NHEADS 2
#define DH     2

__device__ float g_pooled[N_ROWS];
__device__ float g_delta[N_ROWS];

// ---------------------------------------------------------------------------
// Kernel 1: mean over H*W for each (b, nH, hd) row. One block per row.
// ---------------------------------------------------------------------------
__global__ void pool_kernel(const float4* __restrict__ x)
{
    const int row = blockIdx.x;
    const float4* p = x + (size_t)row * HW4;

    float s = 0.0f;
    #pragma unroll
    for (int k = threadIdx.x; k < HW4; k += 128) {
        float4 v = p[k];
        s += (v.x + v.y) + (v.z + v.w);
    }
    // warp reduce
    #pragma unroll
    for (int off = 16; off > 0; off >>= 1)
        s += __shfl_down_sync(0xffffffffu, s, off);

    __shared__ float ws[4];
    if ((threadIdx.x & 31) == 0) ws[threadIdx.x >> 5] = s;
    __syncthreads();
    if (threadIdx.x == 0)
        g_pooled[row] = (ws[0] + ws[1] + ws[2] + ws[3]) * (1.0f / (float)HW);
}

// ---------------------------------------------------------------------------
// Kernel 2: compress -> MHA(L=16, E=4, h=2) -> out_proj -> expand -> LN,
// producing delta[16384]. One block, 256 threads; thread t = (b, l).
// ---------------------------------------------------------------------------
__global__ void tiny_attn_kernel(
    const float* __restrict__ cw,  const float* __restrict__ cb,
    const float* __restrict__ ipw, const float* __restrict__ ipb,
    const float* __restrict__ opw, const float* __restrict__ opb,
    const float* __restrict__ ew,  const float* __restrict__ eb,
    const float* __restrict__ lnw, const float* __restrict__ lnb,
    const float* __restrict__ gate)
{
    __shared__ float s_cw[BN * HD];      // compress_w [4,64]
    __shared__ float s_cb[BN];
    __shared__ float s_ipw[3 * BN * BN]; // in_proj_w [12,4]
    __shared__ float s_ipb[3 * BN];
    __shared__ float s_opw[BN * BN];     // out_proj_w [4,4]
    __shared__ float s_opb[BN];
    __shared__ float s_ew[HD * BN];      // expand_w [64,4]
    __shared__ float s_eb[HD];
    __shared__ float s_lnw[HD];
    __shared__ float s_lnb[HD];
    __shared__ float s_gate;
    __shared__ float s_k[256][BN];
    __shared__ float s_v[256][BN];

    const int t = threadIdx.x;           // 0..255
    // cooperative weight loads
    s_cw[t] = cw[t];
    s_ew[t] = ew[t];
    if (t < BN)        s_cb[t]  = cb[t];
    if (t < 3*BN*BN)   s_ipw[t] = ipw[t];
    if (t < 3*BN)      s_ipb[t] = ipb[t];
    if (t < BN*BN)     s_opw[t] = opw[t];
    if (t >= 64 && t < 64 + BN) s_opb[t - 64] = opb[t - 64];
    if (t < HD)  s_eb[t]  = eb[t];
    if (t >= 64 && t < 128) s_lnw[t - 64] = lnw[t - 64];
    if (t >= 128 && t < 192) s_lnb[t - 128] = lnb[t - 128];
    if (t == 255) s_gate = gate[0];
    __syncthreads();

    const int b = t >> 4;
    const float* prow = g_pooled + t * HD;

    // ---- compress: xc[4] = pooled_row @ compress_w.T + cb ----
    float xc0 = s_cb[0], xc1 = s_cb[1], xc2 = s_cb[2], xc3 = s_cb[3];
    #pragma unroll
    for (int i = 0; i < HD; i++) {
        float p = prow[i];
        xc0 += p * s_cw[i];
        xc1 += p * s_cw[HD + i];
        xc2 += p * s_cw[2*HD + i];
        xc3 += p * s_cw[3*HD + i];
    }
    float xc[BN] = {xc0, xc1, xc2, xc3};

    // ---- qkv = xc @ in_proj_w.T + in_proj_b ----
    float qkv[12];
    #pragma unroll
    for (int r = 0; r < 12; r++) {
        float a = s_ipb[r];
        #pragma unroll
        for (int c = 0; c < BN; c++) a += s_ipw[r * BN + c] * xc[c];
        qkv[r] = a;
    }
    #pragma unroll
    for (int c = 0; c < BN; c++) {
        s_k[t][c] = qkv[4 + c];
        s_v[t][c] = qkv[8 + c];
    }
    __syncthreads();

    // ---- attention per head (h=2, dh=2, keys = 16 tokens of same batch) ----
    const float scale = 0.7071067811865475f;  // 1/sqrt(dh=2)
    float o[BN];
    #pragma unroll
    for (int h = 0; h < NHEADS; h++) {
        const float q0 = qkv[2*h], q1 = qkv[2*h + 1];
        float sc[LSEQ];
        float mx = -1e30f;
        #pragma unroll
        for (int j = 0; j < LSEQ; j++) {
            int kt = (b << 4) + j;
            float s = (q0 * s_k[kt][2*h] + q1 * s_k[kt][2*h + 1]) * scale;
            sc[j] = s;
            mx = fmaxf(mx, s);
        }
        float den = 0.0f, o0 = 0.0f, o1 = 0.0f;
        #pragma unroll
        for (int j = 0; j < LSEQ; j++) {
            int kt = (b << 4) + j;
            float e = __expf(sc[j] - mx);
            den += e;
            o0 += e * s_v[kt][2*h];
            o1 += e * s_v[kt][2*h + 1];
        }
        float inv = 1.0f / den;
        o[2*h]     = o0 * inv;
        o[2*h + 1] = o1 * inv;
    }

    // ---- out_proj ----
    float xa[BN];
    #pragma unroll
    for (int e = 0; e < BN; e++) {
        float a = s_opb[e];
        #pragma unroll
        for (int f = 0; f < BN; f++) a += s_opw[e * BN + f] * o[f];
        xa[e] = a;
    }

    // ---- expand + residual + layernorm -> delta ----
    float y[HD];
    float mu = 0.0f;
    const float gv = s_gate;
    #pragma unroll
    for (int i = 0; i < HD; i++) {
        float ex = s_eb[i];
        #pragma unroll
        for (int f = 0; f < BN; f++) ex += s_ew[i * BN + f] * xa[f];
        float yv = prow[i] + gv * ex;
        y[i] = yv;
        mu += yv;
    }
    mu *= (1.0f / (float)HD);
    float var = 0.0f;
    #pragma unroll
    for (int i = 0; i < HD; i++) {
        float d = y[i] - mu;
        var += d * d;
    }
    var *= (1.0f / (float)HD);
    float inv = rsqrtf(var + 1e-5f);
    #pragma unroll
    for (int i = 0; i < HD; i++) {
        float outv = (y[i] - mu) * inv * s_lnw[i] + s_lnb[i];
        g_delta[t * HD + i] = outv - prow[i];
    }
}

// ---------------------------------------------------------------------------
// Kernel 3: out[row] = x[row] + delta[row]. One block per row, reverse row
// order so the tail of x (still L2-resident from pool_kernel's stream) is
// read first as L2 hits. __ldcs/__stcs = evict-first (read-once / write-once)
// so the out stream doesn't evict still-useful x lines.
// ---------------------------------------------------------------------------
__global__ void add_kernel(const float4* __restrict__ x, float4* __restrict__ out)
{
    const int row = (N_ROWS - 1) - blockIdx.x;   // reverse traversal
    const float d = g_delta[row];
    const float4* p = x + (size_t)row * HW4;
    float4* q = out + (size_t)row * HW4;

    #pragma unroll
    for (int k = threadIdx.x; k < HW4; k += 128) {   // 8 unrolled iterations
        float4 v = __ldcs(p + k);
        v.x += d; v.y += d; v.z += d; v.w += d;
        __stcs(q + k, v);
    }
}

// ---------------------------------------------------------------------------
extern "C" void kernel_launch(void* const* d_in, const int* in_sizes, int n_in,
                              void* d_out, int out_size)
{
    const float* x   = (const float*)d_in[0];
    const float* cw  = (const float*)d_in[1];
    const float* cb  = (const float*)d_in[2];
    const float* ipw = (const float*)d_in[3];
    const float* ipb = (const float*)d_in[4];
    const float* opw = (const float*)d_in[5];
    const float* opb = (const float*)d_in[6];
    const float* ew  = (const float*)d_in[7];
    const float* eb  = (const float*)d_in[8];
    const float* lnw = (const float*)d_in[9];
    const float* lnb = (const float*)d_in[10];
    const float* gate= (const float*)d_in[11];
    float* out = (float*)d_out;

    pool_kernel<<<N_ROWS, 128>>>((const float4*)x);
    tiny_attn_kernel<<<1, 256>>>(cw, cb, ipw, ipb, opw, opb, ew, eb, lnw, lnb, gate);
    add_kernel<<<N_ROWS, 128>>>((const float4*)x, (float4*)out);
}